// round 10
// baseline (speedup 1.0000x reference)
#include <cuda_runtime.h>
#include <cuda_bf16.h>

// Cost volume: out[n,c,d,h,w] = left[n,c,h,w] * right[n,c,h,w-d]  (0 if w<d)
// N=2 C=32 H=136 W=240 D=48, fp32.
//
// Final family: R4 champion shape (8704 CTAs, 256 thr, 8/SM, 59.4us,
// ~6.76 TB/s writes). R10 delta: __stwt (write-through) instead of __stcs —
// output is never re-read and rewritten each replay, so bypassing L2 dirty-
// line allocation may shave the drain. Inner scheme: d = 4q+s -> 2 aligned
// LDS.128 serve 4 disparities; STG.128 write-through.

#define NW   240
#define NH   136
#define NC   32
#define NN   2
#define ND   48
#define W4   60              // float4 columns per row
#define PADF 64              // zero floats in front of P
#define ROWSZ (PADF + NW)    // 304
#define THREADS 256

__global__ __launch_bounds__(THREADS, 8)
void cost_volume_kernel(const float* __restrict__ left,
                        const float* __restrict__ right,
                        float* __restrict__ out) {
    // buf[i] = P[i - PADF]; P[x] = rrow[x] for 0<=x<240, 0 for x<0.
    __shared__ __align__(16) float buf[ROWSZ];

    const int row  = blockIdx.x;         // row = nc * NH + h
    const int h    = row % NH;
    const int nc   = row / NH;
    const int tid  = threadIdx.x;
    const int lane = tid & 31;
    const int wid  = tid >> 5;           // 0..7

    const float* rrow = right + (size_t)row * NW;
    for (int i = tid; i < ROWSZ; i += THREADS)
        buf[i] = (i < PADF) ? 0.0f : rrow[i - PADF];
    __syncthreads();

    // 8 warps: [wid&1] selects column half, [wid>>1] selects d-stripe (12 d's).
    const int c      = lane + ((wid & 1) << 5);   // float4 column 0..63
    const int stripe = wid >> 1;                  // 0..3
    if (c >= W4) return;                          // no collectives below

    const float4 l4 = reinterpret_cast<const float4*>(left + (size_t)row * NW)[c];

    float* obase = out + ((size_t)nc * ND * NH + h) * NW + 4 * c;
    const float* P = buf + PADF;                  // P[x], x down to -64 valid

    #pragma unroll
    for (int g = 0; g < 3; g++) {
        const int q = 3 * stripe + g;             // d-group: d = 4q+s, s=0..3
        // Two aligned 16B smem loads cover all 4 disparities of this group.
        const float4 Y = *reinterpret_cast<const float4*>(P + 4 * (c - q));
        const float4 X = *reinterpret_cast<const float4*>(P + 4 * (c - q - 1));
        const float yv[4] = {Y.x, Y.y, Y.z, Y.w};
        const float xv[4] = {X.x, X.y, X.z, X.w};

        #pragma unroll
        for (int s = 0; s < 4; s++) {
            const int d = 4 * q + s;
            float4 v;
            // out[4c+i] uses P[4c+i-d] = (i>=s) ? Y[i-s] : X[i+4-s]  (static)
            v.x = l4.x * ((0 >= s) ? yv[0] : xv[4 - s]);
            v.y = l4.y * ((1 >= s) ? yv[(1 - s) & 3] : xv[(5 - s) & 3]);
            v.z = l4.z * ((2 >= s) ? yv[(2 - s) & 3] : xv[(6 - s) & 3]);
            v.w = l4.w * ((3 >= s) ? yv[(3 - s) & 3] : xv[(7 - s) & 3]);
            __stwt(reinterpret_cast<float4*>(obase + (size_t)d * (NH * NW)), v);
        }
    }
}

extern "C" void kernel_launch(void* const* d_in, const int* in_sizes, int n_in,
                              void* d_out, int out_size) {
    const float* left  = (const float*)d_in[0];
    const float* right = (const float*)d_in[1];
    float* out = (float*)d_out;

    const int grid = NN * NC * NH;       // 8704 CTAs, one per (n,c,h) row
    cost_volume_kernel<<<grid, THREADS>>>(left, right, out);
}

// round 11
// speedup vs baseline: 1.1378x; 1.1378x over previous
#include <cuda_runtime.h>
#include <cuda_bf16.h>

// Cost volume: out[n,c,d,h,w] = left[n,c,h,w] * right[n,c,h,w-d]  (0 if w<d)
// N=2 C=32 H=136 W=240 D=48, fp32.
//
// FINAL (champion, reproduced 3x at 59.4us = ~6.76 TB/s writes, 88% of HBM
// spec aggregate). Design:
//  - 1 CTA per (n,c,h) row; 8704 CTAs x 256 thr, 8 CTAs/SM.
//  - Right row staged once in smem with a 64-float zero prefix (branch-free
//    exact zero padding for w < d).
//  - d = 4q+s decomposition: TWO aligned LDS.128 (X, Y) serve FOUR whole
//    disparities; component selection is static under full unroll.
//  - Left float4 held in registers (reused 48x).
//  - STG.128 with __stcs (evict-first): L2 write-combines + drains in bursts
//    without hoarding the 401MB output. (__stwt measured -8us worse; scalar
//    LDS and SHFL variants L1/MIO-bound; persistent/barrier variants worse.)

#define NW   240
#define NH   136
#define NC   32
#define NN   2
#define ND   48
#define W4   60              // float4 columns per row
#define PADF 64              // zero floats in front of P
#define ROWSZ (PADF + NW)    // 304
#define THREADS 256

__global__ __launch_bounds__(THREADS, 8)
void cost_volume_kernel(const float* __restrict__ left,
                        const float* __restrict__ right,
                        float* __restrict__ out) {
    // buf[i] = P[i - PADF]; P[x] = rrow[x] for 0<=x<240, 0 for x<0.
    __shared__ __align__(16) float buf[ROWSZ];

    const int row  = blockIdx.x;         // row = nc * NH + h
    const int h    = row % NH;
    const int nc   = row / NH;
    const int tid  = threadIdx.x;
    const int lane = tid & 31;
    const int wid  = tid >> 5;           // 0..7

    const float* rrow = right + (size_t)row * NW;
    for (int i = tid; i < ROWSZ; i += THREADS)
        buf[i] = (i < PADF) ? 0.0f : rrow[i - PADF];
    __syncthreads();

    // 8 warps: [wid&1] selects column half, [wid>>1] selects d-stripe (12 d's).
    const int c      = lane + ((wid & 1) << 5);   // float4 column 0..63
    const int stripe = wid >> 1;                  // 0..3
    if (c >= W4) return;                          // no collectives below

    const float4 l4 = reinterpret_cast<const float4*>(left + (size_t)row * NW)[c];

    float* obase = out + ((size_t)nc * ND * NH + h) * NW + 4 * c;
    const float* P = buf + PADF;                  // P[x], x down to -64 valid

    #pragma unroll
    for (int g = 0; g < 3; g++) {
        const int q = 3 * stripe + g;             // d-group: d = 4q+s, s=0..3
        // Two aligned 16B smem loads cover all 4 disparities of this group.
        const float4 Y = *reinterpret_cast<const float4*>(P + 4 * (c - q));
        const float4 X = *reinterpret_cast<const float4*>(P + 4 * (c - q - 1));
        const float yv[4] = {Y.x, Y.y, Y.z, Y.w};
        const float xv[4] = {X.x, X.y, X.z, X.w};

        #pragma unroll
        for (int s = 0; s < 4; s++) {
            const int d = 4 * q + s;
            float4 v;
            // out[4c+i] uses P[4c+i-d] = (i>=s) ? Y[i-s] : X[i+4-s]  (static)
            v.x = l4.x * ((0 >= s) ? yv[0] : xv[4 - s]);
            v.y = l4.y * ((1 >= s) ? yv[(1 - s) & 3] : xv[(5 - s) & 3]);
            v.z = l4.z * ((2 >= s) ? yv[(2 - s) & 3] : xv[(6 - s) & 3]);
            v.w = l4.w * ((3 >= s) ? yv[(3 - s) & 3] : xv[(7 - s) & 3]);
            __stcs(reinterpret_cast<float4*>(obase + (size_t)d * (NH * NW)), v);
        }
    }
}

extern "C" void kernel_launch(void* const* d_in, const int* in_sizes, int n_in,
                              void* d_out, int out_size) {
    const float* left  = (const float*)d_in[0];
    const float* right = (const float*)d_in[1];
    float* out = (float*)d_out;

    const int grid = NN * NC * NH;       // 8704 CTAs, one per (n,c,h) row
    cost_volume_kernel<<<grid, THREADS>>>(left, right, out);
}